// round 4
// baseline (speedup 1.0000x reference)
#include <cuda_runtime.h>

// y[b,s,d] = x[b,s,d] * gain[d]
// gain[d]  = sum_n cos(n*omega*dt - eps[n,d]*dt),  eps = fe * (1 + 0.1*dw[n]),
//            omega = 1, dt = 0.01
//
// Fused single kernel: each block owns a CHUNK-wide d-slice, computes its gain
// slice into smem (small-angle split: cos(a-b) ~= cosA + sinA*b - 0.5*cosA*b^2,
// b ~ 1e-4 so error ~ b^4 << fp32 ulp), then streams all rows for that slice.

#define CHUNK   1024          // d-elements per block (4 KB smem)
#define THREADS 256           // CHUNK/4 float4 per thread per row
#define MAX_M   32

__global__ void __launch_bounds__(THREADS) fused_kernel(
    const float4* __restrict__ x, float4* __restrict__ out,
    const float* __restrict__ fe, const float* __restrict__ dw,
    int M, int D, int rows)
{
    __shared__ __align__(16) float gain_s[CHUNK];
    __shared__ float s_cos[MAX_M], s_sin[MAX_M], s_scl[MAX_M];

    const int tid   = threadIdx.x;
    const int dbase = blockIdx.x * CHUNK;

    // Per-mode constants: cos(n*0.01), sin(n*0.01), (1+0.1*dw[n])*0.01
    if (tid < M) {
        float a = (float)tid * 0.01f;
        s_cos[tid] = cosf(a);
        s_sin[tid] = sinf(a);
        s_scl[tid] = (1.0f + 0.1f * dw[tid]) * 0.01f;
    }
    __syncthreads();

    // Gain slice for this block's d-chunk (FMA-only, no MUFU in the hot loop).
    for (int dl = tid; dl < CHUNK; dl += THREADS) {
        float acc = 0.0f;
        const float* fep = fe + dbase + dl;
        for (int n = 0; n < M; n++) {
            float b = fep[n * D] * s_scl[n];
            // cosA + sinA*b - 0.5*cosA*b*b
            acc += fmaf(s_sin[n], b, s_cos[n]) - 0.5f * s_cos[n] * b * b;
        }
        gain_s[dl] = acc;
    }
    __syncthreads();

    const float4* g4 = reinterpret_cast<const float4*>(gain_s);
    const float4  g  = g4[tid];                    // fixed per thread, registers
    const int D4  = D >> 2;
    const int db4 = dbase >> 2;

    // Stream all rows for this d-chunk; 1 float4 per thread per row.
    #pragma unroll 4
    for (int r = blockIdx.y; r < rows; r += gridDim.y) {
        size_t idx = (size_t)r * D4 + db4 + tid;
        float4 v = x[idx];
        v.x *= g.x; v.y *= g.y; v.z *= g.z; v.w *= g.w;
        out[idx] = v;
    }
}

// ---------- generic fallback (non-multiple-of-CHUNK D or M > MAX_M) ----------
#define MAX_D 8192
__device__ float g_gain[MAX_D];

__global__ void gain_kernel(const float* __restrict__ fe,
                            const float* __restrict__ dw,
                            int M, int D) {
    int d = blockIdx.x * blockDim.x + threadIdx.x;
    if (d >= D) return;
    const float dt = 0.01f;
    float s = 0.0f;
    for (int n = 0; n < M; n++) {
        float eps = fe[n * D + d] * (1.0f + 0.1f * dw[n]);
        s += cosf((float)n * dt - eps * dt);
    }
    g_gain[d] = s;
}

__global__ void __launch_bounds__(256) scale_kernel_mod(const float4* __restrict__ x,
                                                        float4* __restrict__ out,
                                                        int n4, int d4) {
    int stride = gridDim.x * blockDim.x;
    for (int i = blockIdx.x * blockDim.x + threadIdx.x; i < n4; i += stride) {
        int r = i % d4;
        float4 gv = *reinterpret_cast<const float4*>(&g_gain[r * 4]);
        float4 v = x[i];
        v.x *= gv.x; v.y *= gv.y; v.z *= gv.z; v.w *= gv.w;
        out[i] = v;
    }
}

extern "C" void kernel_launch(void* const* d_in, const int* in_sizes, int n_in,
                              void* d_out, int out_size) {
    const float* x  = (const float*)d_in[0];   // [B, S, D]
    const float* fe = (const float*)d_in[1];   // [M, D]
    const float* dw = (const float*)d_in[2];   // [M]
    // d_in[3] = coupling_matrix, unused by the reference forward.

    int M = in_sizes[2];
    int D = in_sizes[1] / M;
    int total = out_size;          // B*S*D elements
    int rows  = total / D;         // B*S

    if ((D % CHUNK) == 0 && M <= MAX_M && (D / CHUNK) >= 1) {
        dim3 grid(D / CHUNK, 296);        // 4 x 296 = 1184 blocks (8/SM)
        int maxy = rows;
        if ((int)grid.y > maxy) grid.y = maxy;
        fused_kernel<<<grid, THREADS>>>((const float4*)x, (float4*)d_out,
                                        fe, dw, M, D, rows);
    } else {
        int threads = 256;
        gain_kernel<<<(D + threads - 1) / threads, threads>>>(fe, dw, M, D);
        int n4 = total / 4;
        int blocks = 148 * 8;
        int need = (n4 + threads - 1) / threads;
        if (blocks > need) blocks = need;
        scale_kernel_mod<<<blocks, threads>>>((const float4*)x, (float4*)d_out,
                                              n4, D / 4);
    }
}

// round 5
// speedup vs baseline: 1.1908x; 1.1908x over previous
#include <cuda_runtime.h>

// y[b,s,d] = x[b,s,d] * gain[d]
// gain[d]  = sum_n cos(n*omega*dt - eps[n,d]*dt),  eps = fe*(1+0.1*dw[n]),
//            omega=1, dt=0.01
// Small-angle split: b = eps*dt ~ 1e-4, so
//   cos(A - b) = cosA*cos b + sinA*sin b ~= cosA + sinA*b - 0.5*cosA*b^2
// (error ~ b^3/6 * sinA terms ~ 1e-13, far below fp32 ulp). FMA-only, no MUFU
// in the per-d loop; validated at rel_err 6.6e-8 in R4.

#define MAX_D 8192
#define MAX_M 32
__device__ float g_gain[MAX_D];

__global__ void __launch_bounds__(128) gain_kernel(const float* __restrict__ fe,
                                                   const float* __restrict__ dw,
                                                   int M, int D) {
    int d = blockIdx.x * blockDim.x + threadIdx.x;
    if (d >= D) return;

    float s = 0.0f;
    if (M == 16) {
        // Fully unrolled: all 16 fe loads issued up front (MLP=16).
        float b[16];
        #pragma unroll
        for (int n = 0; n < 16; n++)
            b[n] = fe[n * D + d] * ((1.0f + 0.1f * dw[n]) * 0.01f);
        #pragma unroll
        for (int n = 0; n < 16; n++) {
            float a = (float)n * 0.01f;
            float ca = cosf(a), sa = sinf(a);   // compile-time-ish per-n, hoisted
            s += fmaf(sa, b[n], ca) - 0.5f * ca * b[n] * b[n];
        }
    } else {
        for (int n = 0; n < M; n++) {
            float a = (float)n * 0.01f;
            float b = fe[n * D + d] * ((1.0f + 0.1f * dw[n]) * 0.01f);
            s += fmaf(sinf(a), b, cosf(a)) - 0.5f * cosf(a) * b * b;
        }
    }
    g_gain[d] = s;
}

// Streaming kernel: batched independent float4 loads, streaming cache hints.
__global__ void __launch_bounds__(256) scale_kernel(const float4* __restrict__ x,
                                                    float4* __restrict__ out,
                                                    int n4, unsigned d4mask) {
    const int S = gridDim.x * blockDim.x;
    int i = blockIdx.x * blockDim.x + threadIdx.x;

    for (; i + 3 * S < n4; i += 4 * S) {
        // Front-batched loads: 4 independent in flight per thread.
        float4 v0 = __ldcs(&x[i]);
        float4 v1 = __ldcs(&x[i + S]);
        float4 v2 = __ldcs(&x[i + 2 * S]);
        float4 v3 = __ldcs(&x[i + 3 * S]);
        float4 g0 = *reinterpret_cast<const float4*>(&g_gain[((unsigned)(i)         & d4mask) * 4]);
        float4 g1 = *reinterpret_cast<const float4*>(&g_gain[((unsigned)(i + S)     & d4mask) * 4]);
        float4 g2 = *reinterpret_cast<const float4*>(&g_gain[((unsigned)(i + 2 * S) & d4mask) * 4]);
        float4 g3 = *reinterpret_cast<const float4*>(&g_gain[((unsigned)(i + 3 * S) & d4mask) * 4]);
        v0.x *= g0.x; v0.y *= g0.y; v0.z *= g0.z; v0.w *= g0.w;
        v1.x *= g1.x; v1.y *= g1.y; v1.z *= g1.z; v1.w *= g1.w;
        v2.x *= g2.x; v2.y *= g2.y; v2.z *= g2.z; v2.w *= g2.w;
        v3.x *= g3.x; v3.y *= g3.y; v3.z *= g3.z; v3.w *= g3.w;
        __stcs(&out[i],         v0);
        __stcs(&out[i + S],     v1);
        __stcs(&out[i + 2 * S], v2);
        __stcs(&out[i + 3 * S], v3);
    }
    for (; i < n4; i += S) {
        float4 v = __ldcs(&x[i]);
        float4 g = *reinterpret_cast<const float4*>(&g_gain[((unsigned)i & d4mask) * 4]);
        v.x *= g.x; v.y *= g.y; v.z *= g.z; v.w *= g.w;
        __stcs(&out[i], v);
    }
}

// Fallback for non-power-of-two D
__global__ void __launch_bounds__(256) scale_kernel_mod(const float4* __restrict__ x,
                                                        float4* __restrict__ out,
                                                        int n4, int d4) {
    int S = gridDim.x * blockDim.x;
    for (int i = blockIdx.x * blockDim.x + threadIdx.x; i < n4; i += S) {
        int r = i % d4;
        float4 g = *reinterpret_cast<const float4*>(&g_gain[r * 4]);
        float4 v = x[i];
        v.x *= g.x; v.y *= g.y; v.z *= g.z; v.w *= g.w;
        out[i] = v;
    }
}

extern "C" void kernel_launch(void* const* d_in, const int* in_sizes, int n_in,
                              void* d_out, int out_size) {
    const float* x  = (const float*)d_in[0];   // [B, S, D]
    const float* fe = (const float*)d_in[1];   // [M, D]
    const float* dw = (const float*)d_in[2];   // [M]
    // d_in[3] = coupling_matrix, unused by the reference forward.

    int M = in_sizes[2];
    int D = in_sizes[1] / M;
    int total = out_size;          // B*S*D
    int n4 = total / 4;

    // 1. Gain table (fast: FMA-only, MLP=16, spread across 32 blocks)
    {
        int threads = 128;
        int blocks = (D + threads - 1) / threads;
        gain_kernel<<<blocks, threads>>>(fe, dw, M, D);
    }

    // 2. Stream x -> out
    {
        int threads = 256;
        int blocks = 148 * 8;
        int need = (n4 + threads - 1) / threads;
        if (blocks > need) blocks = need;
        int d4 = D / 4;
        if ((d4 & (d4 - 1)) == 0) {
            scale_kernel<<<blocks, threads>>>((const float4*)x, (float4*)d_out,
                                              n4, (unsigned)(d4 - 1));
        } else {
            scale_kernel_mod<<<blocks, threads>>>((const float4*)x, (float4*)d_out,
                                                  n4, d4);
        }
    }
}

// round 6
// speedup vs baseline: 1.2070x; 1.0136x over previous
#include <cuda_runtime.h>

// y[b,s,d] = x[b,s,d] * gain[d]
// gain[d]  = sum_n cos(n*omega*dt - eps[n,d]*dt),  eps = fe*(1+0.1*dw[n]),
//            omega=1, dt=0.01
// Small-angle split (validated rel_err 6.6e-8): b = eps*dt ~ 1e-4,
//   cos(A-b) ~= cosA + sinA*b - 0.5*cosA*b^2
//
// Fully fused single kernel. Grid chosen so stride (in float4) is a multiple
// of D/4 => each thread's d-position is invariant across grid-stride iters.
// Each thread computes its own float4 of gain in a register prologue (16
// coalesced float4 loads from fe, L2-resident), then runs the proven R3
// streaming loop with gain held in registers.

__global__ void __launch_bounds__(256) fused_kernel(
    const float4* __restrict__ x, float4* __restrict__ out,
    const float* __restrict__ fe, const float* __restrict__ dw,
    int M, int n4, unsigned d4mask)
{
    const int i0 = blockIdx.x * blockDim.x + threadIdx.x;
    const unsigned dq = (unsigned)i0 & d4mask;       // float4-group within D
    const int D4 = (int)(d4mask + 1u);

    // ---- Gain prologue (registers only) ----
    const float4* fe4 = reinterpret_cast<const float4*>(fe);
    float gx = 0.f, gy = 0.f, gz = 0.f, gw = 0.f;
    #pragma unroll 16
    for (int n = 0; n < M; n++) {
        float a  = (float)n * 0.01f;
        float ca = cosf(a), sa = sinf(a);
        float scl = fmaf(0.1f, __ldg(&dw[n]), 1.0f) * 0.01f;
        float4 f = __ldg(&fe4[(size_t)n * D4 + dq]);
        float bx = f.x * scl, by = f.y * scl, bz = f.z * scl, bw = f.w * scl;
        gx += fmaf(sa, bx, ca) - 0.5f * ca * bx * bx;
        gy += fmaf(sa, by, ca) - 0.5f * ca * by * by;
        gz += fmaf(sa, bz, ca) - 0.5f * ca * bz * bz;
        gw += fmaf(sa, bw, ca) - 0.5f * ca * bw * bw;
    }

    // ---- Streaming loop (identical shape to the 79.4us R3 kernel) ----
    const int S = gridDim.x * blockDim.x;
    for (int i = i0; i < n4; i += S) {
        float4 v = x[i];
        v.x *= gx; v.y *= gy; v.z *= gz; v.w *= gw;
        out[i] = v;
    }
}

// ---------------- fallback path (generic shapes) ----------------
#define MAX_D 8192
__device__ float g_gain[MAX_D];

__global__ void __launch_bounds__(128) gain_kernel(const float* __restrict__ fe,
                                                   const float* __restrict__ dw,
                                                   int M, int D) {
    int d = blockIdx.x * blockDim.x + threadIdx.x;
    if (d >= D) return;
    float s = 0.0f;
    for (int n = 0; n < M; n++) {
        float a = (float)n * 0.01f;
        float b = fe[n * D + d] * (fmaf(0.1f, dw[n], 1.0f) * 0.01f);
        s += fmaf(sinf(a), b, cosf(a)) - 0.5f * cosf(a) * b * b;
    }
    g_gain[d] = s;
}

__global__ void __launch_bounds__(256) scale_kernel_mod(const float4* __restrict__ x,
                                                        float4* __restrict__ out,
                                                        int n4, int d4) {
    int S = gridDim.x * blockDim.x;
    for (int i = blockIdx.x * blockDim.x + threadIdx.x; i < n4; i += S) {
        int r = i % d4;
        float4 g = *reinterpret_cast<const float4*>(&g_gain[r * 4]);
        float4 v = x[i];
        v.x *= g.x; v.y *= g.y; v.z *= g.z; v.w *= g.w;
        out[i] = v;
    }
}

extern "C" void kernel_launch(void* const* d_in, const int* in_sizes, int n_in,
                              void* d_out, int out_size) {
    const float* x  = (const float*)d_in[0];   // [B, S, D]
    const float* fe = (const float*)d_in[1];   // [M, D]
    const float* dw = (const float*)d_in[2];   // [M]
    // d_in[3] = coupling_matrix, unused by the reference forward.

    int M = in_sizes[2];
    int D = in_sizes[1] / M;
    int total = out_size;          // B*S*D
    int n4 = total / 4;
    int d4 = D / 4;

    bool pow2 = (D % 4 == 0) && ((d4 & (d4 - 1)) == 0);

    // Grid: 1184 blocks (8/SM). Stride = 1184*256 float4; require it to be a
    // multiple of d4 so each thread's d-position is loop-invariant.
    int threads = 256;
    int blocks = 148 * 8;
    int need = (n4 + threads - 1) / threads;
    if (blocks > need) blocks = need;
    bool stride_ok = pow2 && ((blocks * threads) % d4 == 0) && (blocks * threads <= n4 || blocks == need);

    if (stride_ok) {
        fused_kernel<<<blocks, threads>>>((const float4*)x, (float4*)d_out,
                                          fe, dw, M, n4, (unsigned)(d4 - 1));
    } else {
        gain_kernel<<<(D + 127) / 128, 128>>>(fe, dw, M, D);
        scale_kernel_mod<<<blocks, threads>>>((const float4*)x, (float4*)d_out,
                                              n4, d4);
    }
}

// round 7
// speedup vs baseline: 1.2679x; 1.0505x over previous
#include <cuda_runtime.h>

// y[b,s,d] = x[b,s,d] * gain[d]
// gain[d]  = sum_n cos(n*w*dt - eps[n,d]*dt),  eps = fe*(1+0.1*dw[n]), w=1, dt=0.01
//
// Reduction (|b| ~ 1e-4, so O(b^3) terms are ~1e-12, far below fp32 ulp;
// family validated at rel_err 6.6e-8):
//   cos(a_n - b) ~= cos a_n + sin a_n * b - 0.5 cos a_n * b^2
//   gain = C0 + sum_n (p_n + q_n*f) * f
//     with p_n = sin(a_n)*scl_n, q_n = -0.5*cos(a_n)*scl_n^2,
//          scl_n = (1+0.1*dw[n])*0.01,  C0 = sum_n cos(a_n)
// M==16 specialized + fully unrolled => a_n literal => cosf/sinf constant-fold
// => 2 FMA per mode per element, no MUFU.
//
// Grid: stride (in float4) is a multiple of D/4, so each thread's d-position is
// loop-invariant; gain lives in 4 registers. Streaming loop identical to the
// proven 79.4us R3 kernel. __launch_bounds__(256,8) pins 8 CTAs/SM (<=32 regs)
// so the prologue cannot cost streaming occupancy.

__global__ void __launch_bounds__(256, 8) fused_kernel(
    const float4* __restrict__ x, float4* __restrict__ out,
    const float* __restrict__ fe, const float* __restrict__ dw,
    int M, int n4, unsigned d4mask)
{
    const int i0 = blockIdx.x * blockDim.x + threadIdx.x;
    const unsigned dq = (unsigned)i0 & d4mask;       // float4-group within D
    const int D4 = (int)(d4mask + 1u);
    const float4* fe4 = reinterpret_cast<const float4*>(fe);

    float gx, gy, gz, gw;

    if (M == 16) {
        float c0 = 0.f;
        gx = gy = gz = gw = 0.f;
        #pragma unroll
        for (int n = 0; n < 16; n++) {
            const float a  = (float)n * 0.01f;        // literal per unrolled iter
            const float ca = cosf(a);                 // constant-folded
            const float sa = sinf(a);                 // constant-folded
            c0 += ca;
            float scl = fmaf(0.1f, __ldg(&dw[n]), 1.0f) * 0.01f;
            float p = sa * scl;
            float q = -0.5f * ca * scl * scl;
            float4 f = __ldg(&fe4[n * D4 + dq]);
            gx = fmaf(fmaf(q, f.x, p), f.x, gx);
            gy = fmaf(fmaf(q, f.y, p), f.y, gy);
            gz = fmaf(fmaf(q, f.z, p), f.z, gz);
            gw = fmaf(fmaf(q, f.w, p), f.w, gw);
        }
        gx += c0; gy += c0; gz += c0; gw += c0;
    } else {
        gx = gy = gz = gw = 0.f;
        for (int n = 0; n < M; n++) {
            float a  = (float)n * 0.01f;
            float ca = cosf(a), sa = sinf(a);
            float scl = fmaf(0.1f, __ldg(&dw[n]), 1.0f) * 0.01f;
            float p = sa * scl;
            float q = -0.5f * ca * scl * scl;
            float4 f = __ldg(&fe4[n * D4 + dq]);
            gx = fmaf(fmaf(q, f.x, p), f.x, gx + ca);
            gy = fmaf(fmaf(q, f.y, p), f.y, gy + ca);
            gz = fmaf(fmaf(q, f.z, p), f.z, gz + ca);
            gw = fmaf(fmaf(q, f.w, p), f.w, gw + ca);
        }
    }

    // ---- Streaming loop (identical to the proven 79.4us R3 body) ----
    const int S = gridDim.x * blockDim.x;
    for (int i = i0; i < n4; i += S) {
        float4 v = x[i];
        v.x *= gx; v.y *= gy; v.z *= gz; v.w *= gw;
        out[i] = v;
    }
}

// ---------------- fallback path (generic shapes) ----------------
#define MAX_D 8192
__device__ float g_gain[MAX_D];

__global__ void __launch_bounds__(128) gain_kernel(const float* __restrict__ fe,
                                                   const float* __restrict__ dw,
                                                   int M, int D) {
    int d = blockIdx.x * blockDim.x + threadIdx.x;
    if (d >= D) return;
    float s = 0.0f;
    for (int n = 0; n < M; n++) {
        float a = (float)n * 0.01f;
        float b = fe[n * D + d] * (fmaf(0.1f, dw[n], 1.0f) * 0.01f);
        s += fmaf(sinf(a), b, cosf(a)) - 0.5f * cosf(a) * b * b;
    }
    g_gain[d] = s;
}

__global__ void __launch_bounds__(256) scale_kernel_mod(const float4* __restrict__ x,
                                                        float4* __restrict__ out,
                                                        int n4, int d4) {
    int S = gridDim.x * blockDim.x;
    for (int i = blockIdx.x * blockDim.x + threadIdx.x; i < n4; i += S) {
        int r = i % d4;
        float4 g = *reinterpret_cast<const float4*>(&g_gain[r * 4]);
        float4 v = x[i];
        v.x *= g.x; v.y *= g.y; v.z *= g.z; v.w *= g.w;
        out[i] = v;
    }
}

extern "C" void kernel_launch(void* const* d_in, const int* in_sizes, int n_in,
                              void* d_out, int out_size) {
    const float* x  = (const float*)d_in[0];   // [B, S, D]
    const float* fe = (const float*)d_in[1];   // [M, D]
    const float* dw = (const float*)d_in[2];   // [M]
    // d_in[3] = coupling_matrix, unused by the reference forward.

    int M = in_sizes[2];
    int D = in_sizes[1] / M;
    int total = out_size;          // B*S*D
    int n4 = total / 4;
    int d4 = D / 4;

    bool pow2 = (D % 4 == 0) && ((d4 & (d4 - 1)) == 0);

    int threads = 256;
    int blocks = 148 * 8;
    int need = (n4 + threads - 1) / threads;
    if (blocks > need) blocks = need;
    bool stride_ok = pow2 && ((blocks * threads) % d4 == 0);

    if (stride_ok) {
        fused_kernel<<<blocks, threads>>>((const float4*)x, (float4*)d_out,
                                          fe, dw, M, n4, (unsigned)(d4 - 1));
    } else {
        gain_kernel<<<(D + 127) / 128, 128>>>(fe, dw, M, D);
        scale_kernel_mod<<<blocks, threads>>>((const float4*)x, (float4*)d_out,
                                              n4, d4);
    }
}